// round 10
// baseline (speedup 1.0000x reference)
#include <cuda_runtime.h>
#include <cuda_fp16.h>
#include <cstdint>

#define Bb 32
#define Ss 2048
#define Hh 512
#define Ee 512
#define NROWS (Bb*Ss)

#define NFULL 444                     // full M=128 tiles (= 3*148)
#define NHALF 136                     // half M=64 tiles at grid end (LPT)
#define ROWS_FULL (NFULL*128)         // 56832

// ---- device scratch ----
__device__ __half g_Wh[Hh*Hh];
__device__ float  g_dvpart[8*Bb*Hh];
__device__ float  g_wcpart[16*Hh];
__device__ float  g_att[NROWS];
__device__ int    g_done[Bb];         // zero-init; self-resetting

// ---- GEMM geometry ----
#define AS_STRIDE 520
#define BS_STRIDE 72
#define AS_BYTES (128*AS_STRIDE*2)    // 133120
#define BS_BYTES (128*BS_STRIDE*2)    // 18432
#define NSTAGE 3
#define OFF_BS   AS_BYTES
#define OFF_DVEC (OFF_BS + NSTAGE*BS_BYTES)
#define OFF_WC   (OFF_DVEC + 2048)
#define OFF_VW   (OFF_WC + 2048)
#define OFF_COV  (OFF_VW + 2048)
#define OFF_HALF (OFF_COV + 512)
#define SMEM_DYN (OFF_HALF + 1024)    // 196096

__device__ __forceinline__ uint32_t smem_u32(const void* p) {
    uint32_t a;
    asm("{ .reg .u64 t; cvta.to.shared.u64 t, %1; cvt.u32.u64 %0, t; }" : "=r"(a) : "l"(p));
    return a;
}
#define CP16(dst, src) asm volatile("cp.async.cg.shared.global [%0], [%1], 16;" :: "r"(dst), "l"(src))
#define CP_COMMIT()    asm volatile("cp.async.commit_group;" ::: "memory")
#define CP_WAIT1()     asm volatile("cp.async.wait_group 1;" ::: "memory")
#define CP_WAIT0()     asm volatile("cp.async.wait_group 0;" ::: "memory")

#define LDMX4(r0, r1, r2, r3, a) \
    asm volatile("ldmatrix.sync.aligned.m8n8.x4.shared.b16 {%0,%1,%2,%3}, [%4];" \
        : "=r"(r0), "=r"(r1), "=r"(r2), "=r"(r3) : "r"(a))

__device__ __forceinline__ void mma_f16(float* c, const uint32_t* a,
                                        uint32_t b0, uint32_t b1) {
    asm volatile(
        "mma.sync.aligned.m16n8k16.row.col.f32.f16.f16.f32 "
        "{%0,%1,%2,%3}, {%4,%5,%6,%7}, {%8,%9}, {%0,%1,%2,%3};"
        : "+f"(c[0]), "+f"(c[1]), "+f"(c[2]), "+f"(c[3])
        : "r"(a[0]), "r"(a[1]), "r"(a[2]), "r"(a[3]), "r"(b0), "r"(b1));
}

// ---------------------------------------------------------------------------
// prep (528 blocks x 256): unchanged (measured ~10.2us)
// ---------------------------------------------------------------------------
__global__ void prep_kernel(const float* __restrict__ dec_input,
                            const float* __restrict__ W) {
    const int blk = blockIdx.x, tid = threadIdx.x;
    if (blk < 256) {
        __shared__ float t[32][33];
        const int bc = blk & 15, br = blk >> 4;
        const int lx = tid & 31, ly = tid >> 5;
        #pragma unroll
        for (int i = 0; i < 4; i++)
            t[ly + 8*i][lx] = W[(size_t)(br*32 + ly + 8*i)*Hh + bc*32 + lx];
        __syncthreads();
        #pragma unroll
        for (int i = 0; i < 4; i++)
            g_Wh[(size_t)(bc*32 + ly + 8*i)*Hh + br*32 + lx] = __float2half_rn(t[lx][ly + 8*i]);
    } else if (blk < 512) {
        const int loc = blk - 256;
        const int b = loc >> 3, ec = loc & 7;
        __shared__ float sdec[64];
        if (tid < 64) sdec[tid] = dec_input[b*Ee + ec*64 + tid];
        __syncthreads();
        const float* Ws = W + (size_t)(Hh + ec*64) * Hh;
        const int h0 = tid, h1 = tid + 256;
        float a0 = 0.f, a1 = 0.f;
        #pragma unroll 8
        for (int e = 0; e < 64; e++) {
            const float d = sdec[e];
            a0 = fmaf(d, Ws[(size_t)e*Hh + h0], a0);
            a1 = fmaf(d, Ws[(size_t)e*Hh + h1], a1);
        }
        g_dvpart[(size_t)(ec*Bb + b)*Hh + h0] = a0;
        g_dvpart[(size_t)(ec*Bb + b)*Hh + h1] = a1;
    } else {
        const int p = blk - 512;
        const float* Wc = W + (size_t)(Hh + Ee + p*32) * Hh;
        const int h0 = tid, h1 = tid + 256;
        float a0 = 0.f, a1 = 0.f;
        #pragma unroll
        for (int r = 0; r < 32; r++) {
            a0 += Wc[(size_t)r*Hh + h0];
            a1 += Wc[(size_t)r*Hh + h1];
        }
        g_wcpart[p*Hh + h0] = a0;
        g_wcpart[p*Hh + h1] = a1;
    }
}

// ---------------------------------------------------------------------------
// GEMM + fused per-batch softmax. 580 CTAs (444 full + 136 half).
// ---------------------------------------------------------------------------
__global__ __launch_bounds__(256, 1) void gemm_kernel(
    const float* __restrict__ enc,
    const float* __restrict__ cov,
    const float* __restrict__ v_w,
    const float* __restrict__ bias,
    const int* __restrict__ lens,
    float* __restrict__ out)
{
    extern __shared__ char sm[];
    float* s_dvec = (float*)(sm + OFF_DVEC);
    float* s_wc   = (float*)(sm + OFF_WC);
    float* s_vw   = (float*)(sm + OFF_VW);
    float* s_cov  = (float*)(sm + OFF_COV);
    float* s_half = (float*)(sm + OFF_HALF);   // [2][128]
    __shared__ float s_red[9];
    __shared__ int s_last;

    const uint32_t sb = smem_u32(sm);
    const int tid = threadIdx.x;
    const int wid = tid >> 5, lane = tid & 31;
    const int gid = lane >> 2, qid = lane & 3;
    const int wm = wid >> 1, wn = wid & 1;

    const int isFull  = (blockIdx.x < NFULL);
    const int MI      = isFull ? 2 : 1;
    const int mrows   = isFull ? 128 : 64;
    const int rowBand = isFull ? 32 : 16;
    const int row0    = isFull ? blockIdx.x * 128
                               : ROWS_FULL + (blockIdx.x - NFULL) * 64;
    const int b = row0 >> 11;

    const int ldr_n  = tid >> 1;
    const int ldr_k0 = (tid & 1) * 32;
    auto issueB = [&](int q) {
        const int nc = q >> 3, kc = q & 7;
        const uint32_t dst = sb + OFF_BS + (q % NSTAGE)*BS_BYTES + ldr_n*(BS_STRIDE*2) + ldr_k0*2;
        const __half* src = g_Wh + (size_t)(nc*128 + ldr_n)*Hh + kc*64 + ldr_k0;
        #pragma unroll
        for (int j = 0; j < 4; j++)
            CP16(dst + j*16, src + j*8);
    };

    // A chunk loader: chunk c = cols [c*64, c*64+64), all mrows rows.
    const float4* encv = (const float4*)(enc + (size_t)row0 * Hh);
    const int nA = mrows >> 4;         // float4s per thread per chunk (8 / 4)
    auto loadA = [&](int c) {
        #pragma unroll 8
        for (int i = 0; i < nA; i++) {
            int idx = tid + i*256;
            int r = idx >> 4, c4 = idx & 15;
            float4 v = encv[r*128 + c*16 + c4];
            __half2 h0 = __float22half2_rn(make_float2(v.x, v.y));
            __half2 h1 = __float22half2_rn(make_float2(v.z, v.w));
            char* dst = sm + r*(AS_STRIDE*2) + (c*64 + c4*4)*2;
            *(__half2*)dst = h0;
            *(__half2*)(dst + 4) = h1;
        }
    };

    issueB(0); CP_COMMIT();
    issueB(1); CP_COMMIT();

    // epilogue constants
    for (int i = tid; i < Hh; i += 256) {
        float dv = bias[i];
        #pragma unroll
        for (int ec = 0; ec < 8; ec++) dv += g_dvpart[(size_t)(ec*Bb + b)*Hh + i];
        s_dvec[i] = dv;
        float w = 0.f;
        #pragma unroll
        for (int p = 0; p < 16; p++) w += g_wcpart[p*Hh + i];
        s_wc[i] = w;
        s_vw[i] = v_w[i];
    }
    if (tid < mrows) s_cov[tid] = cov[row0 + tid];

    loadA(0);     // only chunk 0 exposed; chunks 1..7 stream during iters 0..6

    const uint32_t baseA = sb
        + (uint32_t)(wm*rowBand + ((lane>>3)&1)*8 + (lane&7)) * (AS_STRIDE*2)
        + (uint32_t)((lane>>4)&1) * 16;
    const uint32_t baseBrow = (uint32_t)(wn*64 + ((lane>>4)&1)*8 + (lane&7)) * (BS_STRIDE*2)
        + (uint32_t)((lane>>3)&1) * 16;

    float p[2][2] = {{0.f, 0.f}, {0.f, 0.f}};
    float acc[2][8][4];

    #pragma unroll 1
    for (int q = 0; q < 32; q++) {
        const int nc = q >> 3, kc = q & 7;
        if (kc == 0) {
            #pragma unroll
            for (int mi = 0; mi < 2; mi++)
                #pragma unroll
                for (int j = 0; j < 8; j++)
                    #pragma unroll
                    for (int c = 0; c < 4; c++) acc[mi][j][c] = 0.f;
        }
        if (q < 31) CP_WAIT1(); else CP_WAIT0();
        __syncthreads();

        const uint32_t bsStage = sb + OFF_BS + (q % NSTAGE)*BS_BYTES + baseBrow;

        #pragma unroll
        for (int ks = 0; ks < 4; ks++) {
            uint32_t a[2][4];
            const uint32_t aAddr = baseA + (uint32_t)(kc*64 + ks*16)*2;
            LDMX4(a[0][0], a[0][1], a[0][2], a[0][3], aAddr);
            if (MI == 2)
                LDMX4(a[1][0], a[1][1], a[1][2], a[1][3], aAddr + 16*(AS_STRIDE*2));

            uint32_t bq[4][4];
            const uint32_t bAddr = bsStage + (uint32_t)(ks*16)*2;
            #pragma unroll
            for (int jp = 0; jp < 4; jp++)
                LDMX4(bq[jp][0], bq[jp][1], bq[jp][2], bq[jp][3],
                      bAddr + (uint32_t)jp*16*(BS_STRIDE*2));

            #pragma unroll
            for (int jp = 0; jp < 4; jp++) {
                mma_f16(acc[0][2*jp],   a[0], bq[jp][0], bq[jp][1]);
                mma_f16(acc[0][2*jp+1], a[0], bq[jp][2], bq[jp][3]);
                if (MI == 2) {
                    mma_f16(acc[1][2*jp],   a[1], bq[jp][0], bq[jp][1]);
                    mma_f16(acc[1][2*jp+1], a[1], bq[jp][2], bq[jp][3]);
                }
            }
        }

        if (q < 7) loadA(q + 1);    // stream next A chunk behind compute

        if (kc == 7) {
            #pragma unroll
            for (int mi = 0; mi < 2; mi++) {
                if (mi >= MI) break;
                const int r0 = wm*rowBand + mi*16 + gid;
                const float cv0 = s_cov[r0], cv1 = s_cov[r0 + 8];
                #pragma unroll
                for (int j = 0; j < 8; j++) {
                    const int n0 = nc*128 + wn*64 + j*8 + qid*2;
                    const float d0 = s_dvec[n0], d1 = s_dvec[n0+1];
                    const float w0 = s_wc[n0],   w1 = s_wc[n0+1];
                    const float v0 = s_vw[n0],   v1 = s_vw[n0+1];
                    float z, t;
                    z = acc[mi][j][0] + d0 + cv0*w0;
                    asm("tanh.approx.f32 %0, %1;" : "=f"(t) : "f"(z));  p[mi][0] = fmaf(v0, t, p[mi][0]);
                    z = acc[mi][j][1] + d1 + cv0*w1;
                    asm("tanh.approx.f32 %0, %1;" : "=f"(t) : "f"(z));  p[mi][0] = fmaf(v1, t, p[mi][0]);
                    z = acc[mi][j][2] + d0 + cv1*w0;
                    asm("tanh.approx.f32 %0, %1;" : "=f"(t) : "f"(z));  p[mi][1] = fmaf(v0, t, p[mi][1]);
                    z = acc[mi][j][3] + d1 + cv1*w1;
                    asm("tanh.approx.f32 %0, %1;" : "=f"(t) : "f"(z));  p[mi][1] = fmaf(v1, t, p[mi][1]);
                }
            }
        }

        if (q < 30) { issueB(q + 2); CP_COMMIT(); }
    }

    // combine partials and store logits
    #pragma unroll
    for (int mi = 0; mi < 2; mi++)
        #pragma unroll
        for (int h = 0; h < 2; h++) {
            float x = p[mi][h];
            x += __shfl_xor_sync(0xffffffffu, x, 1);
            x += __shfl_xor_sync(0xffffffffu, x, 2);
            p[mi][h] = x;
        }
    __syncthreads();
    if (qid == 0) {
        #pragma unroll
        for (int mi = 0; mi < 2; mi++)
            #pragma unroll
            for (int h = 0; h < 2; h++)
                if (mi < MI)
                    s_half[wn*128 + wm*rowBand + mi*16 + gid + h*8] = p[mi][h];
    }
    __syncthreads();
    if (qid == 0 && wn == 0) {
        #pragma unroll
        for (int mi = 0; mi < 2; mi++)
            #pragma unroll
            for (int h = 0; h < 2; h++)
                if (mi < MI) {
                    const int r = wm*rowBand + mi*16 + gid + h*8;
                    g_att[row0 + r] = p[mi][h] + s_half[128 + r];
                }
    }

    // ---- fused per-batch softmax (last-arriver runs it) ----
    __threadfence();
    __syncthreads();
    if (tid == 0) {
        const int target = (b < 27) ? 16 : ((b == 27) ? 20 : 32);
        const int old = atomicAdd(&g_done[b], 1);
        s_last = (old == target - 1) ? 1 : 0;
    }
    __syncthreads();
    if (s_last) {
        __threadfence();
        const int len = lens[b];
        const float NEG_INF = __int_as_float(0xff800000);
        float v[8];
        float mx = NEG_INF;
        #pragma unroll
        for (int j = 0; j < 8; j++) {
            const int i = tid + j*256;
            float x = (i < len) ? g_att[b*Ss + i] : NEG_INF;
            v[j] = x;
            mx = fmaxf(mx, x);
        }
        #pragma unroll
        for (int m = 16; m >= 1; m >>= 1)
            mx = fmaxf(mx, __shfl_xor_sync(0xffffffffu, mx, m));
        if (lane == 0) s_red[wid] = mx;
        __syncthreads();
        if (tid == 0) {
            float m = s_red[0];
            #pragma unroll
            for (int i = 1; i < 8; i++) m = fmaxf(m, s_red[i]);
            s_red[8] = m;
        }
        __syncthreads();
        mx = s_red[8];

        float sum = 0.f;
        #pragma unroll
        for (int j = 0; j < 8; j++) {
            float e = __expf(v[j] - mx);
            v[j] = e;
            sum += e;
        }
        #pragma unroll
        for (int m = 16; m >= 1; m >>= 1)
            sum += __shfl_xor_sync(0xffffffffu, sum, m);
        __syncthreads();
        if (lane == 0) s_red[wid] = sum;
        __syncthreads();
        if (tid == 0) {
            float t = 0.f;
            #pragma unroll
            for (int i = 0; i < 8; i++) t += s_red[i];
            s_red[8] = t;
        }
        __syncthreads();
        const float inv = __fdividef(1.0f, s_red[8]);

        #pragma unroll
        for (int j = 0; j < 8; j++) {
            const int i = tid + j*256;
            const float w = v[j] * inv;
            out[b*Ss + i] = w;
            out[NROWS + b*Ss + i] = cov[b*Ss + i] + w;
        }
        if (tid == 0) g_done[b] = 0;   // reset for next graph replay
    }
}

// ---------------------------------------------------------------------------
extern "C" void kernel_launch(void* const* d_in, const int* in_sizes, int n_in,
                              void* d_out, int out_size) {
    const float* dec_input = (const float*)d_in[0];
    const float* enc       = (const float*)d_in[1];
    const int*   lens      = (const int*)  d_in[2];
    const float* cov       = (const float*)d_in[3];
    const float* W         = (const float*)d_in[4];
    const float* bias      = (const float*)d_in[5];
    const float* v_w       = (const float*)d_in[6];
    float* out = (float*)d_out;

    prep_kernel<<<528, 256>>>(dec_input, W);

    static int configured = 0;
    if (!configured) {
        cudaFuncSetAttribute(gemm_kernel,
                             cudaFuncAttributeMaxDynamicSharedMemorySize, SMEM_DYN);
        configured = 1;
    }
    gemm_kernel<<<NFULL + NHALF, 256, SMEM_DYN>>>(enc, cov, v_w, bias, lens, out);
}

// round 11
// speedup vs baseline: 1.1050x; 1.1050x over previous
#include <cuda_runtime.h>
#include <cuda_fp16.h>
#include <cstdint>

#define Bb 32
#define Ss 2048
#define Hh 512
#define Ee 512
#define NROWS (Bb*Ss)

#define NFULL 444                     // full M=128 tiles (= 3*148)
#define NHALF 136                     // half M=64 tiles at grid end (LPT)
#define ROWS_FULL (NFULL*128)         // 56832

// ---- device scratch ----
__device__ __half g_Wh[Hh*Hh];
__device__ float  g_dvpart[8*Bb*Hh];
__device__ float  g_wcpart[16*Hh];
__device__ float  g_att[NROWS];

// ---- GEMM geometry ----
#define AS_STRIDE 520
#define BS_STRIDE 72
#define AS_BYTES (128*AS_STRIDE*2)    // 133120
#define BS_BYTES (128*BS_STRIDE*2)    // 18432
#define NSTAGE 3
#define OFF_BS   AS_BYTES
#define OFF_DVEC (OFF_BS + NSTAGE*BS_BYTES)
#define OFF_WC   (OFF_DVEC + 2048)
#define OFF_VW   (OFF_WC + 2048)
#define OFF_COV  (OFF_VW + 2048)
#define OFF_HALF (OFF_COV + 512)
#define SMEM_DYN (OFF_HALF + 4*128*4)   // 197120

__device__ __forceinline__ uint32_t smem_u32(const void* p) {
    uint32_t a;
    asm("{ .reg .u64 t; cvta.to.shared.u64 t, %1; cvt.u32.u64 %0, t; }" : "=r"(a) : "l"(p));
    return a;
}
#define CP16(dst, src) asm volatile("cp.async.cg.shared.global [%0], [%1], 16;" :: "r"(dst), "l"(src))
#define CP_COMMIT()    asm volatile("cp.async.commit_group;" ::: "memory")
#define CP_WAIT1()     asm volatile("cp.async.wait_group 1;" ::: "memory")
#define CP_WAIT0()     asm volatile("cp.async.wait_group 0;" ::: "memory")

#define LDMX4(r0, r1, r2, r3, a) \
    asm volatile("ldmatrix.sync.aligned.m8n8.x4.shared.b16 {%0,%1,%2,%3}, [%4];" \
        : "=r"(r0), "=r"(r1), "=r"(r2), "=r"(r3) : "r"(a))

__device__ __forceinline__ void mma_f16(float* c, const uint32_t* a,
                                        uint32_t b0, uint32_t b1) {
    asm volatile(
        "mma.sync.aligned.m16n8k16.row.col.f32.f16.f16.f32 "
        "{%0,%1,%2,%3}, {%4,%5,%6,%7}, {%8,%9}, {%0,%1,%2,%3};"
        : "+f"(c[0]), "+f"(c[1]), "+f"(c[2]), "+f"(c[3])
        : "r"(a[0]), "r"(a[1]), "r"(a[2]), "r"(a[3]), "r"(b0), "r"(b1));
}

// ---------------------------------------------------------------------------
// prep (528 blocks x 256): unchanged
// ---------------------------------------------------------------------------
__global__ void prep_kernel(const float* __restrict__ dec_input,
                            const float* __restrict__ W) {
    const int blk = blockIdx.x, tid = threadIdx.x;
    if (blk < 256) {
        __shared__ float t[32][33];
        const int bc = blk & 15, br = blk >> 4;
        const int lx = tid & 31, ly = tid >> 5;
        #pragma unroll
        for (int i = 0; i < 4; i++)
            t[ly + 8*i][lx] = W[(size_t)(br*32 + ly + 8*i)*Hh + bc*32 + lx];
        __syncthreads();
        #pragma unroll
        for (int i = 0; i < 4; i++)
            g_Wh[(size_t)(bc*32 + ly + 8*i)*Hh + br*32 + lx] = __float2half_rn(t[lx][ly + 8*i]);
    } else if (blk < 512) {
        const int loc = blk - 256;
        const int b = loc >> 3, ec = loc & 7;
        __shared__ float sdec[64];
        if (tid < 64) sdec[tid] = dec_input[b*Ee + ec*64 + tid];
        __syncthreads();
        const float* Ws = W + (size_t)(Hh + ec*64) * Hh;
        const int h0 = tid, h1 = tid + 256;
        float a0 = 0.f, a1 = 0.f;
        #pragma unroll 8
        for (int e = 0; e < 64; e++) {
            const float d = sdec[e];
            a0 = fmaf(d, Ws[(size_t)e*Hh + h0], a0);
            a1 = fmaf(d, Ws[(size_t)e*Hh + h1], a1);
        }
        g_dvpart[(size_t)(ec*Bb + b)*Hh + h0] = a0;
        g_dvpart[(size_t)(ec*Bb + b)*Hh + h1] = a1;
    } else {
        const int p = blk - 512;
        const float* Wc = W + (size_t)(Hh + Ee + p*32) * Hh;
        const int h0 = tid, h1 = tid + 256;
        float a0 = 0.f, a1 = 0.f;
        #pragma unroll
        for (int r = 0; r < 32; r++) {
            a0 += Wc[(size_t)r*Hh + h0];
            a1 += Wc[(size_t)r*Hh + h1];
        }
        g_wcpart[p*Hh + h0] = a0;
        g_wcpart[p*Hh + h1] = a1;
    }
}

// ---------------------------------------------------------------------------
// GEMM: 580 CTAs (444 full + 136 half), 512 threads (16 warps = 4M x 4N).
// Per N-chunk: warp covers 32 rows x 32 cols. Single barrier per iteration.
// ---------------------------------------------------------------------------
__global__ __launch_bounds__(512, 1) void gemm_kernel(
    const float* __restrict__ enc,
    const float* __restrict__ cov,
    const float* __restrict__ v_w,
    const float* __restrict__ bias)
{
    extern __shared__ char sm[];
    float* s_dvec = (float*)(sm + OFF_DVEC);
    float* s_wc   = (float*)(sm + OFF_WC);
    float* s_vw   = (float*)(sm + OFF_VW);
    float* s_cov  = (float*)(sm + OFF_COV);
    float* s_half = (float*)(sm + OFF_HALF);   // [4][128]

    const uint32_t sb = smem_u32(sm);
    const int tid = threadIdx.x;
    const int wid = tid >> 5, lane = tid & 31;
    const int gid = lane >> 2, qid = lane & 3;
    const int wm = wid >> 2, wn = wid & 3;     // 4 x 4 warp grid

    const int isFull  = (blockIdx.x < NFULL);
    const int MI      = isFull ? 2 : 1;
    const int mrows   = isFull ? 128 : 64;
    const int rowBand = isFull ? 32 : 16;
    const int row0    = isFull ? blockIdx.x * 128
                               : ROWS_FULL + (blockIdx.x - NFULL) * 64;
    const int b = row0 >> 11;

    // B loader: 512 threads, each 2x CP16 per chunk
    const int ldr_n  = tid >> 2;               // 0..127
    const int ldr_k0 = (tid & 3) * 16;         // halves
    auto issueB = [&](int q) {
        const int nc = q >> 3, kc = q & 7;
        const uint32_t dst = sb + OFF_BS + (q % NSTAGE)*BS_BYTES + ldr_n*(BS_STRIDE*2) + ldr_k0*2;
        const __half* src = g_Wh + (size_t)(nc*128 + ldr_n)*Hh + kc*64 + ldr_k0;
        CP16(dst,      src);
        CP16(dst + 16, src + 8);
    };

    issueB(0); CP_COMMIT();
    issueB(1); CP_COMMIT();

    // epilogue constants
    for (int i = tid; i < Hh; i += 512) {
        float dv = bias[i];
        #pragma unroll
        for (int ec = 0; ec < 8; ec++) dv += g_dvpart[(size_t)(ec*Bb + b)*Hh + i];
        s_dvec[i] = dv;
        float w = 0.f;
        #pragma unroll
        for (int p = 0; p < 16; p++) w += g_wcpart[p*Hh + i];
        s_wc[i] = w;
        s_vw[i] = v_w[i];
    }
    if (tid < mrows) s_cov[tid] = cov[row0 + tid];

    // A tile upfront: mrows x 512 fp32 -> fp16 smem
    {
        const float4* encv = (const float4*)(enc + (size_t)row0 * Hh);
        const int nIter = mrows >> 2;   // 32 or 16
        #pragma unroll 8
        for (int i = 0; i < nIter; i++) {
            int idx = tid + i*512;
            int r = idx >> 7, c4 = idx & 127;
            float4 v = encv[r*128 + c4];
            __half2 h0 = __float22half2_rn(make_float2(v.x, v.y));
            __half2 h1 = __float22half2_rn(make_float2(v.z, v.w));
            char* dst = sm + r*(AS_STRIDE*2) + c4*8;
            *(__half2*)dst = h0;
            *(__half2*)(dst + 4) = h1;
        }
    }
    // q=0 barrier below orders A stores before fragment reads.

    const uint32_t baseA = sb
        + (uint32_t)(wm*rowBand + ((lane>>3)&1)*8 + (lane&7)) * (AS_STRIDE*2)
        + (uint32_t)((lane>>4)&1) * 16;
    const uint32_t baseBrow = (uint32_t)(wn*32 + ((lane>>4)&1)*8 + (lane&7)) * (BS_STRIDE*2)
        + (uint32_t)((lane>>3)&1) * 16;

    float p[2][2] = {{0.f, 0.f}, {0.f, 0.f}};
    float acc[2][4][4];

    #pragma unroll 1
    for (int q = 0; q < 32; q++) {
        const int nc = q >> 3, kc = q & 7;
        if (kc == 0) {
            #pragma unroll
            for (int mi = 0; mi < 2; mi++)
                #pragma unroll
                for (int j = 0; j < 4; j++)
                    #pragma unroll
                    for (int c = 0; c < 4; c++) acc[mi][j][c] = 0.f;
        }
        if (q < 31) CP_WAIT1(); else CP_WAIT0();
        __syncthreads();

        const uint32_t bsStage = sb + OFF_BS + (q % NSTAGE)*BS_BYTES + baseBrow;

        #pragma unroll
        for (int ks = 0; ks < 4; ks++) {
            uint32_t a[2][4];
            const uint32_t aAddr = baseA + (uint32_t)(kc*64 + ks*16)*2;
            LDMX4(a[0][0], a[0][1], a[0][2], a[0][3], aAddr);
            if (MI == 2)
                LDMX4(a[1][0], a[1][1], a[1][2], a[1][3], aAddr + 16*(AS_STRIDE*2));

            uint32_t bq[2][4];
            const uint32_t bAddr = bsStage + (uint32_t)(ks*16)*2;
            #pragma unroll
            for (int jp = 0; jp < 2; jp++)
                LDMX4(bq[jp][0], bq[jp][1], bq[jp][2], bq[jp][3],
                      bAddr + (uint32_t)jp*16*(BS_STRIDE*2));

            #pragma unroll
            for (int jp = 0; jp < 2; jp++) {
                mma_f16(acc[0][2*jp],   a[0], bq[jp][0], bq[jp][1]);
                mma_f16(acc[0][2*jp+1], a[0], bq[jp][2], bq[jp][3]);
                if (MI == 2) {
                    mma_f16(acc[1][2*jp],   a[1], bq[jp][0], bq[jp][1]);
                    mma_f16(acc[1][2*jp+1], a[1], bq[jp][2], bq[jp][3]);
                }
            }
        }

        if (kc == 7) {
            #pragma unroll
            for (int mi = 0; mi < 2; mi++) {
                if (mi >= MI) break;
                const int r0 = wm*rowBand + mi*16 + gid;
                const float cv0 = s_cov[r0], cv1 = s_cov[r0 + 8];
                #pragma unroll
                for (int j = 0; j < 4; j++) {
                    const int n0 = nc*128 + wn*32 + j*8 + qid*2;
                    const float d0 = s_dvec[n0], d1 = s_dvec[n0+1];
                    const float w0 = s_wc[n0],   w1 = s_wc[n0+1];
                    const float v0 = s_vw[n0],   v1 = s_vw[n0+1];
                    float z, t;
                    z = acc[mi][j][0] + d0 + cv0*w0;
                    asm("tanh.approx.f32 %0, %1;" : "=f"(t) : "f"(z));  p[mi][0] = fmaf(v0, t, p[mi][0]);
                    z = acc[mi][j][1] + d1 + cv0*w1;
                    asm("tanh.approx.f32 %0, %1;" : "=f"(t) : "f"(z));  p[mi][0] = fmaf(v1, t, p[mi][0]);
                    z = acc[mi][j][2] + d0 + cv1*w0;
                    asm("tanh.approx.f32 %0, %1;" : "=f"(t) : "f"(z));  p[mi][1] = fmaf(v0, t, p[mi][1]);
                    z = acc[mi][j][3] + d1 + cv1*w1;
                    asm("tanh.approx.f32 %0, %1;" : "=f"(t) : "f"(z));  p[mi][1] = fmaf(v1, t, p[mi][1]);
                }
            }
        }

        if (q < 30) { issueB(q + 2); CP_COMMIT(); }
    }

    // reduce over qid lanes; combine the 4 wn bands via smem; store
    #pragma unroll
    for (int mi = 0; mi < 2; mi++)
        #pragma unroll
        for (int h = 0; h < 2; h++) {
            float x = p[mi][h];
            x += __shfl_xor_sync(0xffffffffu, x, 1);
            x += __shfl_xor_sync(0xffffffffu, x, 2);
            p[mi][h] = x;
        }
    __syncthreads();
    if (qid == 0) {
        #pragma unroll
        for (int mi = 0; mi < 2; mi++)
            #pragma unroll
            for (int h = 0; h < 2; h++)
                if (mi < MI)
                    s_half[wn*128 + wm*rowBand + mi*16 + gid + h*8] = p[mi][h];
    }
    __syncthreads();
    if (qid == 0 && wn == 0) {
        #pragma unroll
        for (int mi = 0; mi < 2; mi++)
            #pragma unroll
            for (int h = 0; h < 2; h++)
                if (mi < MI) {
                    const int r = wm*rowBand + mi*16 + gid + h*8;
                    g_att[row0 + r] = p[mi][h] + s_half[128 + r]
                                    + s_half[256 + r] + s_half[384 + r];
                }
    }
}

// ---------------------------------------------------------------------------
// softmax + coverage: separate kernel (round-9 version)
// ---------------------------------------------------------------------------
__global__ __launch_bounds__(512) void softmax_kernel(
    const int* __restrict__ lens,
    const float* __restrict__ cov,
    float* __restrict__ out)
{
    __shared__ float red[17];
    const int b = blockIdx.x;
    const int tid = threadIdx.x;
    const int len = lens[b];
    const float NEG_INF = __int_as_float(0xff800000);

    float v[4];
    float mx = NEG_INF;
    #pragma unroll
    for (int j = 0; j < 4; j++) {
        const int i = tid + j*512;
        float x = (i < len) ? g_att[b*Ss + i] : NEG_INF;
        v[j] = x;
        mx = fmaxf(mx, x);
    }
    #pragma unroll
    for (int m = 16; m >= 1; m >>= 1)
        mx = fmaxf(mx, __shfl_xor_sync(0xffffffffu, mx, m));
    if ((tid & 31) == 0) red[tid >> 5] = mx;
    __syncthreads();
    if (tid == 0) {
        float m = red[0];
        #pragma unroll
        for (int i = 1; i < 16; i++) m = fmaxf(m, red[i]);
        red[16] = m;
    }
    __syncthreads();
    mx = red[16];

    float sum = 0.f;
    #pragma unroll
    for (int j = 0; j < 4; j++) {
        float e = __expf(v[j] - mx);
        v[j] = e;
        sum += e;
    }
    #pragma unroll
    for (int m = 16; m >= 1; m >>= 1)
        sum += __shfl_xor_sync(0xffffffffu, sum, m);
    __syncthreads();
    if ((tid & 31) == 0) red[tid >> 5] = sum;
    __syncthreads();
    if (tid == 0) {
        float t = 0.f;
        #pragma unroll
        for (int i = 0; i < 16; i++) t += red[i];
        red[16] = t;
    }
    __syncthreads();
    const float inv = __fdividef(1.0f, red[16]);

    #pragma unroll
    for (int j = 0; j < 4; j++) {
        const int i = tid + j*512;
        const float w = v[j] * inv;
        out[b*Ss + i] = w;
        out[NROWS + b*Ss + i] = cov[b*Ss + i] + w;
    }
}

// ---------------------------------------------------------------------------
extern "C" void kernel_launch(void* const* d_in, const int* in_sizes, int n_in,
                              void* d_out, int out_size) {
    const float* dec_input = (const float*)d_in[0];
    const float* enc       = (const float*)d_in[1];
    const int*   lens      = (const int*)  d_in[2];
    const float* cov       = (const float*)d_in[3];
    const float* W         = (const float*)d_in[4];
    const float* bias      = (const float*)d_in[5];
    const float* v_w       = (const float*)d_in[6];
    float* out = (float*)d_out;

    prep_kernel<<<528, 256>>>(dec_input, W);

    static int configured = 0;
    if (!configured) {
        cudaFuncSetAttribute(gemm_kernel,
                             cudaFuncAttributeMaxDynamicSharedMemorySize, SMEM_DYN);
        configured = 1;
    }
    gemm_kernel<<<NFULL + NHALF, 512, SMEM_DYN>>>(enc, cov, v_w, bias);

    softmax_kernel<<<Bb, 512>>>(lens, cov, out);
}